// round 2
// baseline (speedup 1.0000x reference)
#include <cuda_runtime.h>
#include <cuda_bf16.h>
#include <cstdint>

// Linear_36146444763339: block-diagonal equivariant linear.
// out[n, off_l + w*d + i] = ALPHA * sum_u x[n, off_l + u*d + i] * W_l[u, w]
// for blocks l in {0,1,2} with d in {1,3,5}, offsets {0,128,512}, MUL=128.
//
// Strategy (round 1): warp-level mma.sync bf16 with hi/lo split (3 passes)
// for fp32-grade accuracy, fp32 accumulate. One CTA = 128 rows x one
// (block, i) slice. Grid x = 9 slices (fastest-varying bid) so slices of the
// same row-tile are concurrent and share L2 lines of the stride-d columns.

#define FEATS 1152
#define MUL 128
#define TILE_M 128
#define NTHREADS 256
#define AS_STRIDE 132   // fp32 elements per A row (padded, conflict-free frag loads)
#define WS_STRIDE 136   // bf16 elements per W row (padded)
#define ALPHA_F 0.08838834764831845f  // 1/sqrt(128)

#define AS_BYTES (TILE_M * AS_STRIDE * 4)          // 67584
#define WS_BYTES (MUL * WS_STRIDE * 2)             // 34816
#define SMEM_BYTES (AS_BYTES + 2 * WS_BYTES)       // 137216

__device__ __forceinline__ void mma16816(float* c, const uint32_t* a,
                                         uint32_t b0, uint32_t b1) {
    asm volatile(
        "mma.sync.aligned.m16n8k16.row.col.f32.bf16.bf16.f32 "
        "{%0,%1,%2,%3}, {%4,%5,%6,%7}, {%8,%9}, {%0,%1,%2,%3};"
        : "+f"(c[0]), "+f"(c[1]), "+f"(c[2]), "+f"(c[3])
        : "r"(a[0]), "r"(a[1]), "r"(a[2]), "r"(a[3]), "r"(b0), "r"(b1));
}

// Split a float2 into packed bf16x2 hi and lo (residual) parts.
// Low 16 bits of the b32 = first (lower-k) element, as mma expects.
__device__ __forceinline__ void split2(float2 v, uint32_t& h, uint32_t& l) {
    __nv_bfloat162 hb = __float22bfloat162_rn(v);
    float2 r = make_float2(v.x - __bfloat162float(hb.x),
                           v.y - __bfloat162float(hb.y));
    __nv_bfloat162 lb = __float22bfloat162_rn(r);
    h = *reinterpret_cast<uint32_t*>(&hb);
    l = *reinterpret_cast<uint32_t*>(&lb);
}

__global__ __launch_bounds__(NTHREADS, 1)
void Linear_36146444763339_kernel(
    const float* __restrict__ x,
    const float* __restrict__ w0,
    const float* __restrict__ w1,
    const float* __restrict__ w2,
    float* __restrict__ out,
    int ntot)
{
    // Slice decode: blockIdx.x in [0,9) -> (block l, component i)
    int s = blockIdx.x;
    int i, off, d;
    const float* w;
    if (s == 0)      { i = 0;     off = 0;   d = 1; w = w0; }
    else if (s < 4)  { i = s - 1; off = 128; d = 3; w = w1; }
    else             { i = s - 4; off = 512; d = 5; w = w2; }

    extern __shared__ unsigned char smem_raw[];
    float* As = reinterpret_cast<float*>(smem_raw);
    __nv_bfloat16* Wh = reinterpret_cast<__nv_bfloat16*>(smem_raw + AS_BYTES);
    __nv_bfloat16* Wl = reinterpret_cast<__nv_bfloat16*>(smem_raw + AS_BYTES + WS_BYTES);

    const int tid = threadIdx.x;
    const long n0 = (long)blockIdx.y * TILE_M;

    // ---- Stage W^T (hi/lo bf16) into SMEM: Wh[w_][u] = bf16(W[u][w_]) ----
    // Coalesced global read; one-time strided STS.
    for (int idx = tid; idx < MUL * MUL; idx += NTHREADS) {
        int u  = idx >> 7;
        int ww = idx & 127;
        float v = w[idx];
        __nv_bfloat16 h = __float2bfloat16(v);
        float r = v - __bfloat162float(h);
        Wh[ww * WS_STRIDE + u] = h;
        Wl[ww * WS_STRIDE + u] = __float2bfloat16(r);
    }

    // ---- Stage A (fp32) into SMEM: As[m][u] = x[n0+m, off + u*d + i] ----
    for (int idx = tid; idx < TILE_M * MUL; idx += NTHREADS) {
        int m = idx >> 7;
        int u = idx & 127;
        long n = n0 + m;
        float v = 0.0f;
        if (n < ntot) v = x[n * FEATS + off + (long)u * d + i];
        As[m * AS_STRIDE + u] = v;
    }
    __syncthreads();

    // ---- MMA mainloop: each warp owns m16 x n128, K=128 in 8 steps ----
    const int warp = tid >> 5;
    const int lane = tid & 31;
    const int g = lane >> 2;   // group id (row within frag)
    const int t = lane & 3;    // thread in group
    const int m0 = warp * 16;

    float acc[16][4];
#pragma unroll
    for (int j = 0; j < 16; j++)
#pragma unroll
        for (int r = 0; r < 4; r++) acc[j][r] = 0.0f;

    const float* rowA0 = As + (m0 + g) * AS_STRIDE + 2 * t;
    const float* rowA1 = As + (m0 + g + 8) * AS_STRIDE + 2 * t;

#pragma unroll
    for (int ks = 0; ks < 8; ks++) {
        const int kb = ks * 16;
        // A fragments (m16k16): rows g / g+8, k halves 0-7 / 8-15
        float2 v0 = *reinterpret_cast<const float2*>(rowA0 + kb);
        float2 v1 = *reinterpret_cast<const float2*>(rowA1 + kb);
        float2 v2 = *reinterpret_cast<const float2*>(rowA0 + kb + 8);
        float2 v3 = *reinterpret_cast<const float2*>(rowA1 + kb + 8);
        uint32_t ah[4], al[4];
        split2(v0, ah[0], al[0]);
        split2(v1, ah[1], al[1]);
        split2(v2, ah[2], al[2]);
        split2(v3, ah[3], al[3]);

#pragma unroll
        for (int j = 0; j < 16; j++) {
            const int wrow = (8 * j + g) * WS_STRIDE + kb + 2 * t;
            uint32_t bh0 = *reinterpret_cast<const uint32_t*>(Wh + wrow);
            uint32_t bh1 = *reinterpret_cast<const uint32_t*>(Wh + wrow + 8);
            uint32_t bl0 = *reinterpret_cast<const uint32_t*>(Wl + wrow);
            uint32_t bl1 = *reinterpret_cast<const uint32_t*>(Wl + wrow + 8);
            mma16816(acc[j], ah, bh0, bh1);   // hi * hi
            mma16816(acc[j], ah, bl0, bl1);   // hi * lo
            mma16816(acc[j], al, bh0, bh1);   // lo * hi
        }
    }

    // ---- Epilogue: scale by ALPHA, scatter to strided output columns ----
#pragma unroll
    for (int j = 0; j < 16; j++) {
#pragma unroll
        for (int r = 0; r < 4; r++) {
            int row = m0 + g + ((r >> 1) << 3);
            int col = 8 * j + 2 * t + (r & 1);          // output w index
            long n = n0 + row;
            if (n < ntot)
                out[n * FEATS + off + (long)col * d + i] = acc[j][r] * ALPHA_F;
        }
    }
}

extern "C" void kernel_launch(void* const* d_in, const int* in_sizes, int n_in,
                              void* d_out, int out_size) {
    const float* x  = (const float*)d_in[0];
    const float* w0 = (const float*)d_in[1];
    const float* w1 = (const float*)d_in[2];
    const float* w2 = (const float*)d_in[3];
    float* out = (float*)d_out;
    const int ntot = in_sizes[0] / FEATS;
    const int tiles = (ntot + TILE_M - 1) / TILE_M;

    // Idempotent, capture-safe (not a stream op).
    cudaFuncSetAttribute(Linear_36146444763339_kernel,
                         cudaFuncAttributeMaxDynamicSharedMemorySize, SMEM_BYTES);

    dim3 grid(9, tiles);  // slices fastest-varying: same-tile slices share L2 lines
    Linear_36146444763339_kernel<<<grid, NTHREADS, SMEM_BYTES>>>(
        x, w0, w1, w2, out, ntot);
}

// round 3
// speedup vs baseline: 1.3644x; 1.3644x over previous
#include <cuda_runtime.h>
#include <cuda_bf16.h>
#include <cstdint>

// Block-diagonal equivariant linear (e3nn-style):
// out[n, off_l + w*d + i] = ALPHA * sum_u x[n, off_l + u*d + i] * W_l[u, w]
// blocks l: d in {1,3,5}, offsets {0,128,512}, MUL=128, FEAT=1152.
//
// Round 2: persistent CTAs (W staged once), cp.async double-buffered A gather,
// warp tile m32 x n64, 3-pass bf16 hi/lo MMA with fp32 accumulate.

#define FEATS 1152
#define NT 256
#define AS_STRIDE 136                 // fp32 words per A row (conflict-free LDS.64)
#define WS_STRIDE 136                 // bf16 elems per W^T row (conflict-free LDS.32)
#define AS_ELEMS (128 * AS_STRIDE)
#define AS_BYTES (AS_ELEMS * 4)       // 69632
#define WS_BYTES (128 * WS_STRIDE * 2) // 34816
#define SMEM_BYTES (2 * AS_BYTES + 2 * WS_BYTES)  // 208896
#define ALPHA_F 0.08838834764831845f  // 1/sqrt(128)
#define NCTAS 144

__device__ __forceinline__ void mma16816(float* c, const uint32_t* a,
                                         uint32_t b0, uint32_t b1) {
    asm volatile(
        "mma.sync.aligned.m16n8k16.row.col.f32.bf16.bf16.f32 "
        "{%0,%1,%2,%3}, {%4,%5,%6,%7}, {%8,%9}, {%0,%1,%2,%3};"
        : "+f"(c[0]), "+f"(c[1]), "+f"(c[2]), "+f"(c[3])
        : "r"(a[0]), "r"(a[1]), "r"(a[2]), "r"(a[3]), "r"(b0), "r"(b1));
}

__device__ __forceinline__ void split2(float2 v, uint32_t& h, uint32_t& l) {
    __nv_bfloat162 hb = __float22bfloat162_rn(v);
    float2 r = make_float2(v.x - __bfloat162float(hb.x),
                           v.y - __bfloat162float(hb.y));
    __nv_bfloat162 lb = __float22bfloat162_rn(r);
    h = *reinterpret_cast<uint32_t*>(&hb);
    l = *reinterpret_cast<uint32_t*>(&lb);
}

// Async-gather one 128-row A tile (strided columns) into smem buffer, zfill OOB.
__device__ __forceinline__ void issue_tile(const float* __restrict__ x,
                                           int off, int d, int i,
                                           long n0, int ntot,
                                           float* Abuf, int tid) {
    uint32_t sbase = (uint32_t)__cvta_generic_to_shared(Abuf);
    int m = tid >> 7;                  // 0 or 1
    int u = tid & 127;
    const float* g = x + (n0 + m) * FEATS + off + (long)u * d + i;
    uint32_t sa = sbase + (uint32_t)(m * AS_STRIDE + u) * 4u;
    long n = n0 + m;
#pragma unroll
    for (int it = 0; it < 64; it++) {   // rows m, m+2, ..., m+126
        int sz = (n < ntot) ? 4 : 0;
        asm volatile("cp.async.ca.shared.global [%0], [%1], 4, %2;\n"
                     :: "r"(sa), "l"(g), "r"(sz));
        g += 2 * FEATS;
        sa += 2 * AS_STRIDE * 4;
        n += 2;
    }
}

__global__ __launch_bounds__(NT, 1)
void Linear_36146444763339_kernel(
    const float* __restrict__ x,
    const float* __restrict__ w0,
    const float* __restrict__ w1,
    const float* __restrict__ w2,
    float* __restrict__ out,
    int ntot)
{
    // ---- Persistent slice decode: 144 CTAs over 9 slices, weighted by cost ----
    const int cnts[9] = {12, 14, 14, 14, 18, 18, 18, 18, 18};
    int bx = blockIdx.x;
    int s = 0, base = 0;
#pragma unroll
    for (int q = 0; q < 8; q++) {
        if (bx >= base + cnts[q]) { base += cnts[q]; s = q + 1; }
    }
    const int sub = bx - base;       // this CTA's index within the slice
    const int stride = cnts[s];      // CTAs working this slice

    int i, off, d;
    const float* w;
    if (s == 0)      { i = 0;     off = 0;   d = 1; w = w0; }
    else if (s < 4)  { i = s - 1; off = 128; d = 3; w = w1; }
    else             { i = s - 4; off = 512; d = 5; w = w2; }

    extern __shared__ unsigned char smem_raw[];
    float* As = reinterpret_cast<float*>(smem_raw);                        // 2 buffers
    __nv_bfloat16* Wh = reinterpret_cast<__nv_bfloat16*>(smem_raw + 2 * AS_BYTES);
    __nv_bfloat16* Wl = reinterpret_cast<__nv_bfloat16*>(smem_raw + 2 * AS_BYTES + WS_BYTES);

    const int tid = threadIdx.x;
    const int ntiles = (ntot + 127) >> 7;

    // ---- Stage W^T (hi/lo bf16, ALPHA folded) once per CTA ----
    for (int idx = tid; idx < 128 * 128; idx += NT) {
        int u  = idx >> 7;
        int ww = idx & 127;
        float v = w[idx] * ALPHA_F;
        __nv_bfloat16 h = __float2bfloat16(v);
        float r = v - __bfloat162float(h);
        Wh[ww * WS_STRIDE + u] = h;
        Wl[ww * WS_STRIDE + u] = __float2bfloat16(r);
    }

    // ---- Prologue: prefetch tiles sub, sub+stride ----
    issue_tile(x, off, d, i, (long)sub << 7, ntot, As, tid);
    asm volatile("cp.async.commit_group;\n");
    {
        long t1 = (long)(sub + stride);
        if (t1 < ntiles)
            issue_tile(x, off, d, i, t1 << 7, ntot, As + AS_ELEMS, tid);
        asm volatile("cp.async.commit_group;\n");
    }

    // ---- Warp tiling: 4 (m) x 2 (n) warps, each m32 x n64 ----
    const int warp = tid >> 5;
    const int lane = tid & 31;
    const int g = lane >> 2;
    const int t = lane & 3;
    const int m0 = (warp & 3) * 32;
    const int nw0 = (warp >> 2) * 64;

    int cur = 0;
    for (long k = sub; k < ntiles; k += stride) {
        asm volatile("cp.async.wait_group 1;\n");
        __syncthreads();

        const float* Ab = As + cur * AS_ELEMS;
        const long n0 = k << 7;

        float acc[2][8][4];
#pragma unroll
        for (int mi = 0; mi < 2; mi++)
#pragma unroll
            for (int j = 0; j < 8; j++)
#pragma unroll
                for (int r = 0; r < 4; r++) acc[mi][j][r] = 0.0f;

#pragma unroll
        for (int ks = 0; ks < 8; ks++) {
            const int kb = ks * 16;
            uint32_t ah[2][4], al[2][4];
#pragma unroll
            for (int mi = 0; mi < 2; mi++) {
                const float* r0 = Ab + (m0 + mi * 16 + g) * AS_STRIDE + kb + 2 * t;
                const float* r1 = r0 + 8 * AS_STRIDE;
                split2(*reinterpret_cast<const float2*>(r0),     ah[mi][0], al[mi][0]);
                split2(*reinterpret_cast<const float2*>(r1),     ah[mi][1], al[mi][1]);
                split2(*reinterpret_cast<const float2*>(r0 + 8), ah[mi][2], al[mi][2]);
                split2(*reinterpret_cast<const float2*>(r1 + 8), ah[mi][3], al[mi][3]);
            }
#pragma unroll
            for (int j = 0; j < 8; j++) {
                const int wrow = (nw0 + 8 * j + g) * WS_STRIDE + kb + 2 * t;
                uint32_t bh0 = *reinterpret_cast<const uint32_t*>(Wh + wrow);
                uint32_t bh1 = *reinterpret_cast<const uint32_t*>(Wh + wrow + 8);
                uint32_t bl0 = *reinterpret_cast<const uint32_t*>(Wl + wrow);
                uint32_t bl1 = *reinterpret_cast<const uint32_t*>(Wl + wrow + 8);
#pragma unroll
                for (int mi = 0; mi < 2; mi++) {
                    mma16816(acc[mi][j], ah[mi], bh0, bh1);   // hi*hi
                    mma16816(acc[mi][j], ah[mi], bl0, bl1);   // hi*lo
                    mma16816(acc[mi][j], al[mi], bh0, bh1);   // lo*hi
                }
            }
        }

        // All warps done reading Ab -> safe to refill this buffer.
        __syncthreads();
        {
            long nxt = k + 2 * (long)stride;
            if (nxt < ntiles)
                issue_tile(x, off, d, i, nxt << 7, ntot, As + cur * AS_ELEMS, tid);
            asm volatile("cp.async.commit_group;\n");
        }

        // ---- Epilogue: scatter to strided output columns (ALPHA pre-folded) ----
#pragma unroll
        for (int mi = 0; mi < 2; mi++) {
#pragma unroll
            for (int j = 0; j < 8; j++) {
#pragma unroll
                for (int r = 0; r < 4; r++) {
                    int row = m0 + mi * 16 + g + ((r >> 1) << 3);
                    int col = nw0 + 8 * j + 2 * t + (r & 1);
                    long n = n0 + row;
                    if (n < ntot)
                        out[n * FEATS + off + (long)col * d + i] = acc[mi][j][r];
                }
            }
        }
        cur ^= 1;
    }
}

extern "C" void kernel_launch(void* const* d_in, const int* in_sizes, int n_in,
                              void* d_out, int out_size) {
    const float* x  = (const float*)d_in[0];
    const float* w0 = (const float*)d_in[1];
    const float* w1 = (const float*)d_in[2];
    const float* w2 = (const float*)d_in[3];
    float* out = (float*)d_out;
    const int ntot = in_sizes[0] / FEATS;

    cudaFuncSetAttribute(Linear_36146444763339_kernel,
                         cudaFuncAttributeMaxDynamicSharedMemorySize, SMEM_BYTES);

    Linear_36146444763339_kernel<<<NCTAS, NT, SMEM_BYTES>>>(x, w0, w1, w2, out, ntot);
}